// round 9
// baseline (speedup 1.0000x reference)
#include <cuda_runtime.h>

// Problem constants: B=2, N=1024, T=64, H=64
#define NN 1024

// Scratch (allocation-free rule: __device__ globals)
// p/q layout: [h][n][b] interleaved -> element (h,n,b) at (h*1024+n)*2+b
__device__ float g_p[2 * 64 * NN];
__device__ float g_q[2 * 64 * NN];
__device__ float g_U[NN];
__device__ float g_V[NN];
__device__ float g_pv[NN * 16];      // per-(row, col-tile) partial max value
__device__ int   g_pi[NN * 16];      // per-(row, col-tile) partial argmax j
// cross-block tail state (reset by last k2 block each run)
__device__ int   g_rowcnt[32];
__device__ int   g_done;

// ---------------------------------------------------------------------------
// Kernel 1: per-node projections. 256 blocks x 256 threads, 4 nodes/block.
// Thread = (h = tid>>2, nn = tid&3). W1 read directly from gmem (L1-cached,
// 4-lane broadcast) -- no smem staging.
// ---------------------------------------------------------------------------
__global__ void __launch_bounds__(256) k1_proj(
    const float* __restrict__ x, const float* __restrict__ W1,
    const float* __restrict__ b1, const float* __restrict__ W2,
    const float* __restrict__ b2) {
    __shared__ __align__(16) float sx[2][4][68];   // x rows, pitch 68
    __shared__ float sUV[2][32];                   // warp partials [sel][w*4+nn]

    const int tid = threadIdx.x;
    const int n0 = blockIdx.x * 4;

    #pragma unroll
    for (int k = 0; k < 2; ++k) {             // x: 512 floats
        int l = k * 256 + tid;
        int b = l >> 8, node = (l >> 6) & 3, t = l & 63;
        sx[b][node][t] = x[((b << 10) + n0 + node) * 64 + t];
    }
    __syncthreads();

    const int h = tid >> 2;       // 0..63
    const int nn = tid & 3;       // 0..3
    const float4* __restrict__ wrow = (const float4*)(W1 + h * 128);

    float p0 = 0.f, p1 = 0.f, q0 = 0.f, q1 = 0.f;
    #pragma unroll
    for (int tt = 0; tt < 16; ++tt) {
        float4 wa = __ldg(&wrow[tt]);
        float4 wb = __ldg(&wrow[16 + tt]);
        float4 xa = *(const float4*)&sx[0][nn][tt * 4];
        float4 xb = *(const float4*)&sx[1][nn][tt * 4];
        p0 = fmaf(xa.x, wa.x, p0); p0 = fmaf(xa.y, wa.y, p0);
        p0 = fmaf(xa.z, wa.z, p0); p0 = fmaf(xa.w, wa.w, p0);
        p1 = fmaf(xb.x, wa.x, p1); p1 = fmaf(xb.y, wa.y, p1);
        p1 = fmaf(xb.z, wa.z, p1); p1 = fmaf(xb.w, wa.w, p1);
        q0 = fmaf(xa.x, wb.x, q0); q0 = fmaf(xa.y, wb.y, q0);
        q0 = fmaf(xa.z, wb.z, q0); q0 = fmaf(xa.w, wb.w, q0);
        q1 = fmaf(xb.x, wb.x, q1); q1 = fmaf(xb.y, wb.y, q1);
        q1 = fmaf(xb.z, wb.z, q1); q1 = fmaf(xb.w, wb.w, q1);
    }
    float bb = __ldg(&b1[h]);
    q0 += bb; q1 += bb;

    *(float2*)&g_p[(h * 1024 + n0 + nn) * 2] = make_float2(p0, p1);
    *(float2*)&g_q[(h * 1024 + n0 + nn) * 2] = make_float2(q0, q1);

    float w2h = __ldg(&W2[h]);
    float ru = w2h * (p0 + p1), rv = w2h * (q0 + q1);
    #pragma unroll
    for (int m = 16; m >= 4; m >>= 1) {
        ru += __shfl_down_sync(0xffffffffu, ru, m);
        rv += __shfl_down_sync(0xffffffffu, rv, m);
    }
    if ((tid & 31) < 4) {
        int w = tid >> 5;
        sUV[0][w * 4 + nn] = ru;
        sUV[1][w * 4 + nn] = rv;
    }
    __syncthreads();
    if (tid < 8) {
        int sel = tid >> 2, n2 = tid & 3;
        float acc = 0.f;
        #pragma unroll
        for (int w = 0; w < 8; ++w) acc += sUV[sel][w * 4 + n2];
        if (sel == 0) g_U[n0 + n2] = 0.2525f * acc;
        else          g_V[n0 + n2] = 0.2525f * acc + __ldg(&b2[0]);
    }
}

// ---------------------------------------------------------------------------
// Kernel 2: pairwise |z| accumulation + fused gumbel/argmax + finisher tail.
// Tile 32(i) x 64(j); grid (16, 32) = 512 blocks -> all resident in one wave
// at 4 blocks/SM. Block 16x16 threads, 2i x 4j x 2b per thread.
// smem: ps[32][64] 8KB + qs[32][128] 16KB = 24.3KB.
// ---------------------------------------------------------------------------
__global__ void __launch_bounds__(256, 4) k2_pair(const float* __restrict__ W2,
                                                  const float* __restrict__ gu,
                                                  float* __restrict__ out) {
    __shared__ __align__(16) float ps[32][64];     // [h][i*2+b] chunk
    __shared__ __align__(16) float qs[32][128];    // [h][j*2+b] chunk
    __shared__ float sw[64];
    __shared__ int s_old;

    const int tx = threadIdx.x, ty = threadIdx.y;
    const int tid = ty * 16 + tx;
    const int bx = blockIdx.x, by = blockIdx.y;
    const int i0 = by * 32, j0 = bx * 64;

    if (tid < 64) sw[tid] = 0.2475f * W2[tid];

    float acc[2][4];
    #pragma unroll
    for (int r = 0; r < 2; ++r)
        #pragma unroll
        for (int c = 0; c < 4; ++c) acc[r][c] = 0.f;

    #pragma unroll
    for (int hc = 0; hc < 2; ++hc) {
        const int hb = hc * 32;
        const float* __restrict__ pgc = g_p + (hb * 1024 + i0) * 2;
        const float* __restrict__ qgc = g_q + (hb * 1024 + j0) * 2;
        __syncthreads();   // protect prior chunk (and sw on first iter)
        #pragma unroll
        for (int k = 0; k < 2; ++k) {            // ps: 512 f4
            int l = k * 256 + tid;
            int hh = l >> 4, f4 = l & 15;
            *(float4*)&ps[hh][f4 << 2] = *(const float4*)&pgc[hh * 2048 + (f4 << 2)];
        }
        #pragma unroll
        for (int k = 0; k < 4; ++k) {            // qs: 1024 f4
            int l = k * 256 + tid;
            int hh = l >> 5, f4 = l & 31;
            *(float4*)&qs[hh][f4 << 2] = *(const float4*)&qgc[hh * 2048 + (f4 << 2)];
        }
        __syncthreads();

        #pragma unroll 4
        for (int h = 0; h < 32; ++h) {
            float w = sw[hb + h];
            float4 pA = *(const float4*)&ps[h][ty << 2];        // i r=0,1 (b0,b1)
            float4 qA = *(const float4*)&qs[h][tx << 3];
            float4 qB = *(const float4*)&qs[h][(tx << 3) + 4];
            float pv[4] = {pA.x, pA.y, pA.z, pA.w};
            float qv[8] = {qA.x, qA.y, qA.z, qA.w, qB.x, qB.y, qB.z, qB.w};
            #pragma unroll
            for (int r = 0; r < 2; ++r)
                #pragma unroll
                for (int c = 0; c < 4; ++c) {
                    float z0 = pv[2 * r]     + qv[2 * c];
                    float z1 = pv[2 * r + 1] + qv[2 * c + 1];
                    acc[r][c] = fmaf(w, fabsf(z0), acc[r][c]);
                    acc[r][c] = fmaf(w, fabsf(z1), acc[r][c]);
                }
        }
    }

    float u[2], v[4];
    #pragma unroll
    for (int r = 0; r < 2; ++r) u[r] = g_U[i0 + (ty << 1) + r];
    #pragma unroll
    for (int c = 0; c < 4; ++c) v[c] = g_V[j0 + (tx << 2) + c];

    float vrow[2][4];
    #pragma unroll
    for (int r = 0; r < 2; ++r)
        #pragma unroll
        for (int c = 0; c < 4; ++c)
            vrow[r][c] = acc[r][c] + u[r] + v[c];

    // zero-fill this out tile (ones written by the finisher tail)
    const float4 z4 = make_float4(0.f, 0.f, 0.f, 0.f);
    #pragma unroll
    for (int r = 0; r < 2; ++r)
        *(float4*)&out[(i0 + (ty << 1) + r) * 1024 + j0 + (tx << 2)] = z4;

    // gumbel + per-row argmax across the 16 tx lanes
    #pragma unroll
    for (int r = 0; r < 2; ++r) {
        const int row = i0 + (ty << 1) + r;
        float4 uu = *(const float4*)&gu[row * 1024 + j0 + (tx << 2)];
        float gq[4];
        gq[0] = -__logf(-__logf(uu.x + 1e-10f) + 1e-10f);
        gq[1] = -__logf(-__logf(uu.y + 1e-10f) + 1e-10f);
        gq[2] = -__logf(-__logf(uu.z + 1e-10f) + 1e-10f);
        gq[3] = -__logf(-__logf(uu.w + 1e-10f) + 1e-10f);
        float bv = -3.0e38f; int bj = 1 << 30;
        #pragma unroll
        for (int c = 0; c < 4; ++c) {
            float val = vrow[r][c] + gq[c];
            int j = j0 + (tx << 2) + c;
            if (val > bv || (val == bv && j < bj)) { bv = val; bj = j; }
        }
        #pragma unroll
        for (int m = 1; m < 16; m <<= 1) {
            float ov = __shfl_xor_sync(0xffffffffu, bv, m);
            int   oj = __shfl_xor_sync(0xffffffffu, bj, m);
            if (ov > bv || (ov == bv && oj < bj)) { bv = ov; bj = oj; }
        }
        if (tx == 0) {
            g_pv[row * 16 + bx] = bv;
            g_pi[row * 16 + bx] = bj;
        }
    }

    // ------- finisher tail: 16th block of row-band reduces + scatters -------
    __threadfence();
    __syncthreads();
    if (tid == 0) s_old = atomicAdd(&g_rowcnt[by], 1);
    __syncthreads();
    if (s_old == 15) {
        __threadfence();               // see all partials + zero-fills
        if (tid < 32) {
            const int row = by * 32 + tid;
            float bv = -3.0e38f; int bj = 1 << 30;
            #pragma unroll
            for (int k4 = 0; k4 < 4; ++k4) {
                float4 v4 = *(const float4*)&g_pv[row * 16 + k4 * 4];
                int4   j4 = *(const int4*)&g_pi[row * 16 + k4 * 4];
                float vv[4] = {v4.x, v4.y, v4.z, v4.w};
                int   jj[4] = {j4.x, j4.y, j4.z, j4.w};
                #pragma unroll
                for (int k = 0; k < 4; ++k)
                    if (vv[k] > bv || (vv[k] == bv && jj[k] < bj)) { bv = vv[k]; bj = jj[k]; }
            }
            out[row * 1024 + bj] = 1.0f;
        }
    }
    // last block overall resets tail state for the next graph replay
    if (tid == 0) {
        int old2 = atomicAdd(&g_done, 1);
        if (old2 == 511) {
            #pragma unroll
            for (int s = 0; s < 32; ++s) g_rowcnt[s] = 0;
            g_done = 0;
        }
    }
}

// ---------------------------------------------------------------------------
extern "C" void kernel_launch(void* const* d_in, const int* in_sizes, int n_in,
                              void* d_out, int out_size) {
    const float* x  = (const float*)d_in[0];   // [2,1024,64]
    const float* W1 = (const float*)d_in[1];   // [64,128]
    const float* b1 = (const float*)d_in[2];   // [64]
    const float* W2 = (const float*)d_in[3];   // [1,64]
    const float* b2 = (const float*)d_in[4];   // [1]
    const float* gu = (const float*)d_in[5];   // [1024,1024]
    float* out = (float*)d_out;                // [1024,1024] fp32

    k1_proj<<<256, 256>>>(x, W1, b1, W2, b2);
    k2_pair<<<dim3(16, 32), dim3(16, 16)>>>(W2, gu, out);
}

// round 10
// speedup vs baseline: 1.0482x; 1.0482x over previous
#include <cuda_runtime.h>

// Problem constants: B=2, N=1024, T=64, H=64
#define NN 1024

// Scratch (allocation-free rule: __device__ globals)
// p/q layout: [h][n][b] interleaved -> element (h,n,b) at (h*1024+n)*2+b
__device__ float g_p[2 * 64 * NN];
__device__ float g_q[2 * 64 * NN];
__device__ float g_U[NN];
__device__ float g_V[NN];
__device__ float g_pv[NN * 8];       // per-(row, col-tile) partial max value
__device__ int   g_pi[NN * 8];       // per-(row, col-tile) partial argmax j
// cross-block tail state (reset by last k2 block each run)
__device__ int   g_rowcnt[16];
__device__ int   g_done;

// ---------------------------------------------------------------------------
// Kernel 1: per-node projections. 256 blocks x 256 threads, 4 nodes/block.
// Thread = (h = tid>>2, nn = tid&3). W1 read directly from gmem (L1-cached,
// 4-lane broadcast) -- no smem staging.
// ---------------------------------------------------------------------------
__global__ void __launch_bounds__(256) k1_proj(
    const float* __restrict__ x, const float* __restrict__ W1,
    const float* __restrict__ b1, const float* __restrict__ W2,
    const float* __restrict__ b2) {
    __shared__ __align__(16) float sx[2][4][68];   // x rows, pitch 68
    __shared__ float sUV[2][32];                   // warp partials [sel][w*4+nn]

    const int tid = threadIdx.x;
    const int n0 = blockIdx.x * 4;

    #pragma unroll
    for (int k = 0; k < 2; ++k) {             // x: 512 floats
        int l = k * 256 + tid;
        int b = l >> 8, node = (l >> 6) & 3, t = l & 63;
        sx[b][node][t] = x[((b << 10) + n0 + node) * 64 + t];
    }
    __syncthreads();

    const int h = tid >> 2;       // 0..63
    const int nn = tid & 3;       // 0..3
    const float4* __restrict__ wrow = (const float4*)(W1 + h * 128);

    float p0 = 0.f, p1 = 0.f, q0 = 0.f, q1 = 0.f;
    #pragma unroll
    for (int tt = 0; tt < 16; ++tt) {
        float4 wa = __ldg(&wrow[tt]);
        float4 wb = __ldg(&wrow[16 + tt]);
        float4 xa = *(const float4*)&sx[0][nn][tt * 4];
        float4 xb = *(const float4*)&sx[1][nn][tt * 4];
        p0 = fmaf(xa.x, wa.x, p0); p0 = fmaf(xa.y, wa.y, p0);
        p0 = fmaf(xa.z, wa.z, p0); p0 = fmaf(xa.w, wa.w, p0);
        p1 = fmaf(xb.x, wa.x, p1); p1 = fmaf(xb.y, wa.y, p1);
        p1 = fmaf(xb.z, wa.z, p1); p1 = fmaf(xb.w, wa.w, p1);
        q0 = fmaf(xa.x, wb.x, q0); q0 = fmaf(xa.y, wb.y, q0);
        q0 = fmaf(xa.z, wb.z, q0); q0 = fmaf(xa.w, wb.w, q0);
        q1 = fmaf(xb.x, wb.x, q1); q1 = fmaf(xb.y, wb.y, q1);
        q1 = fmaf(xb.z, wb.z, q1); q1 = fmaf(xb.w, wb.w, q1);
    }
    float bb = __ldg(&b1[h]);
    q0 += bb; q1 += bb;

    *(float2*)&g_p[(h * 1024 + n0 + nn) * 2] = make_float2(p0, p1);
    *(float2*)&g_q[(h * 1024 + n0 + nn) * 2] = make_float2(q0, q1);

    float w2h = __ldg(&W2[h]);
    float ru = w2h * (p0 + p1), rv = w2h * (q0 + q1);
    #pragma unroll
    for (int m = 16; m >= 4; m >>= 1) {
        ru += __shfl_down_sync(0xffffffffu, ru, m);
        rv += __shfl_down_sync(0xffffffffu, rv, m);
    }
    if ((tid & 31) < 4) {
        int w = tid >> 5;
        sUV[0][w * 4 + nn] = ru;
        sUV[1][w * 4 + nn] = rv;
    }
    __syncthreads();
    if (tid < 8) {
        int sel = tid >> 2, n2 = tid & 3;
        float acc = 0.f;
        #pragma unroll
        for (int w = 0; w < 8; ++w) acc += sUV[sel][w * 4 + n2];
        if (sel == 0) g_U[n0 + n2] = 0.2525f * acc;
        else          g_V[n0 + n2] = 0.2525f * acc + __ldg(&b2[0]);
    }
}

// ---------------------------------------------------------------------------
// Kernel 2: pairwise |z| accumulation + fused gumbel/argmax + finisher tail.
// Tile 64(i) x 128(j); grid (8, 16) = 128 blocks, block 16x16 threads.
// Per-thread 4i x 8j x 2b = 128 fma-ops per h for 6 LDS.128 (ratio 21).
// h chunked by 16: smem ps[16][128] 8KB + qs[16][256] 16KB = 24.6KB.
// ---------------------------------------------------------------------------
__global__ void __launch_bounds__(256) k2_pair(const float* __restrict__ W2,
                                               const float* __restrict__ gu,
                                               float* __restrict__ out) {
    __shared__ __align__(16) float ps[16][128];    // [h][i*2+b] chunk
    __shared__ __align__(16) float qs[16][256];    // [h][j*2+b] chunk
    __shared__ float sw[64];
    __shared__ int s_old;

    const int tx = threadIdx.x, ty = threadIdx.y;
    const int tid = ty * 16 + tx;
    const int bx = blockIdx.x, by = blockIdx.y;    // bx: j-tile 0..7, by: i-tile 0..15
    const int i0 = by * 64, j0 = bx * 128;

    if (tid < 64) sw[tid] = 0.2475f * W2[tid];

    float acc[4][8];
    #pragma unroll
    for (int r = 0; r < 4; ++r)
        #pragma unroll
        for (int c = 0; c < 8; ++c) acc[r][c] = 0.f;

    #pragma unroll
    for (int hc = 0; hc < 4; ++hc) {
        const int hb = hc * 16;
        const float* __restrict__ pgc = g_p + (hb * 1024 + i0) * 2;
        const float* __restrict__ qgc = g_q + (hb * 1024 + j0) * 2;
        __syncthreads();   // protect prior chunk (and sw on first iter)
        #pragma unroll
        for (int k = 0; k < 2; ++k) {            // ps: 512 f4
            int l = k * 256 + tid;
            int hh = l >> 5, f4 = l & 31;
            *(float4*)&ps[hh][f4 << 2] = *(const float4*)&pgc[hh * 2048 + (f4 << 2)];
        }
        #pragma unroll
        for (int k = 0; k < 4; ++k) {            // qs: 1024 f4
            int l = k * 256 + tid;
            int hh = l >> 6, f4 = l & 63;
            *(float4*)&qs[hh][f4 << 2] = *(const float4*)&qgc[hh * 2048 + (f4 << 2)];
        }
        __syncthreads();

        #pragma unroll 2
        for (int h = 0; h < 16; ++h) {
            float w = sw[hb + h];
            float4 pA = *(const float4*)&ps[h][ty << 3];        // i r=0,1 (b0,b1)
            float4 pB = *(const float4*)&ps[h][(ty << 3) + 4];  // i r=2,3
            float4 qA = *(const float4*)&qs[h][tx << 4];
            float4 qB = *(const float4*)&qs[h][(tx << 4) + 4];
            float4 qC = *(const float4*)&qs[h][(tx << 4) + 8];
            float4 qD = *(const float4*)&qs[h][(tx << 4) + 12];
            float pv[8] = {pA.x, pA.y, pA.z, pA.w, pB.x, pB.y, pB.z, pB.w};
            float qv[16] = {qA.x, qA.y, qA.z, qA.w, qB.x, qB.y, qB.z, qB.w,
                            qC.x, qC.y, qC.z, qC.w, qD.x, qD.y, qD.z, qD.w};
            #pragma unroll
            for (int r = 0; r < 4; ++r)
                #pragma unroll
                for (int c = 0; c < 8; ++c) {
                    float z0 = pv[2 * r]     + qv[2 * c];
                    float z1 = pv[2 * r + 1] + qv[2 * c + 1];
                    acc[r][c] = fmaf(w, fabsf(z0), acc[r][c]);
                    acc[r][c] = fmaf(w, fabsf(z1), acc[r][c]);
                }
        }
    }

    float u[4], v[8];
    #pragma unroll
    for (int r = 0; r < 4; ++r) u[r] = g_U[i0 + (ty << 2) + r];
    #pragma unroll
    for (int c = 0; c < 8; ++c) v[c] = g_V[j0 + (tx << 3) + c];

    // zero-fill this out tile (ones written by the finisher tail)
    const float4 z4 = make_float4(0.f, 0.f, 0.f, 0.f);
    #pragma unroll
    for (int r = 0; r < 4; ++r) {
        *(float4*)&out[(i0 + (ty << 2) + r) * 1024 + j0 + (tx << 3)] = z4;
        *(float4*)&out[(i0 + (ty << 2) + r) * 1024 + j0 + (tx << 3) + 4] = z4;
    }

    // gumbel + per-row argmax across the 16 tx lanes
    #pragma unroll
    for (int r = 0; r < 4; ++r) {
        const int row = i0 + (ty << 2) + r;
        float4 uu0 = *(const float4*)&gu[row * 1024 + j0 + (tx << 3)];
        float4 uu1 = *(const float4*)&gu[row * 1024 + j0 + (tx << 3) + 4];
        float gq[8];
        gq[0] = -__logf(-__logf(uu0.x + 1e-10f) + 1e-10f);
        gq[1] = -__logf(-__logf(uu0.y + 1e-10f) + 1e-10f);
        gq[2] = -__logf(-__logf(uu0.z + 1e-10f) + 1e-10f);
        gq[3] = -__logf(-__logf(uu0.w + 1e-10f) + 1e-10f);
        gq[4] = -__logf(-__logf(uu1.x + 1e-10f) + 1e-10f);
        gq[5] = -__logf(-__logf(uu1.y + 1e-10f) + 1e-10f);
        gq[6] = -__logf(-__logf(uu1.z + 1e-10f) + 1e-10f);
        gq[7] = -__logf(-__logf(uu1.w + 1e-10f) + 1e-10f);
        float bv = -3.0e38f; int bj = 1 << 30;
        #pragma unroll
        for (int c = 0; c < 8; ++c) {
            float val = acc[r][c] + u[r] + v[c] + gq[c];
            int j = j0 + (tx << 3) + c;
            if (val > bv || (val == bv && j < bj)) { bv = val; bj = j; }
        }
        #pragma unroll
        for (int m = 1; m < 16; m <<= 1) {
            float ov = __shfl_xor_sync(0xffffffffu, bv, m);
            int   oj = __shfl_xor_sync(0xffffffffu, bj, m);
            if (ov > bv || (ov == bv && oj < bj)) { bv = ov; bj = oj; }
        }
        if (tx == 0) {
            g_pv[row * 8 + bx] = bv;
            g_pi[row * 8 + bx] = bj;
        }
    }

    // ------- finisher tail: 8th block of row-band reduces + scatters -------
    __threadfence();
    __syncthreads();
    if (tid == 0) s_old = atomicAdd(&g_rowcnt[by], 1);
    __syncthreads();
    if (s_old == 7) {
        __threadfence();               // see all partials + zero-fills
        if (tid < 64) {
            const int row = by * 64 + tid;
            float bv = -3.0e38f; int bj = 1 << 30;
            #pragma unroll
            for (int k4 = 0; k4 < 2; ++k4) {
                float4 v4 = *(const float4*)&g_pv[row * 8 + k4 * 4];
                int4   j4 = *(const int4*)&g_pi[row * 8 + k4 * 4];
                float vv[4] = {v4.x, v4.y, v4.z, v4.w};
                int   jj[4] = {j4.x, j4.y, j4.z, j4.w};
                #pragma unroll
                for (int k = 0; k < 4; ++k)
                    if (vv[k] > bv || (vv[k] == bv && jj[k] < bj)) { bv = vv[k]; bj = jj[k]; }
            }
            out[row * 1024 + bj] = 1.0f;
        }
    }
    // last block overall resets tail state for the next graph replay
    if (tid == 0) {
        int old2 = atomicAdd(&g_done, 1);
        if (old2 == 127) {
            #pragma unroll
            for (int s = 0; s < 16; ++s) g_rowcnt[s] = 0;
            g_done = 0;
        }
    }
}

// ---------------------------------------------------------------------------
extern "C" void kernel_launch(void* const* d_in, const int* in_sizes, int n_in,
                              void* d_out, int out_size) {
    const float* x  = (const float*)d_in[0];   // [2,1024,64]
    const float* W1 = (const float*)d_in[1];   // [64,128]
    const float* b1 = (const float*)d_in[2];   // [64]
    const float* W2 = (const float*)d_in[3];   // [1,64]
    const float* b2 = (const float*)d_in[4];   // [1]
    const float* gu = (const float*)d_in[5];   // [1024,1024]
    float* out = (float*)d_out;                // [1024,1024] fp32

    k1_proj<<<256, 256>>>(x, W1, b1, W2, b2);
    k2_pair<<<dim3(8, 16), dim3(16, 16)>>>(W2, gu, out);
}

// round 11
// speedup vs baseline: 1.3726x; 1.3095x over previous
#include <cuda_runtime.h>

// Problem constants: B=2, N=1024, T=64, H=64
#define NN 1024

// Scratch (allocation-free rule: __device__ globals)
// p/q layout: plain [b][h][n] -> element (b,h,n) at b*65536 + h*1024 + n
__device__ float g_p[2 * 64 * NN];
__device__ float g_q[2 * 64 * NN];
__device__ float g_U[NN];
__device__ float g_V[NN];
__device__ float g_pv[NN * 16];      // per-(row, col-tile) partial max value
__device__ int   g_pi[NN * 16];      // per-(row, col-tile) partial argmax j
// cross-block tail state (reset by last k2 block each run)
__device__ int   g_rowcnt[16];
__device__ int   g_done;

// ---------------------------------------------------------------------------
// Kernel 1: per-node projections. 256 blocks x 256 threads, 4 nodes/block.
// Thread = (h = tid>>2, nn = tid&3). W1 read directly from gmem (L1-cached,
// 4-lane broadcast) -- no smem staging.
// ---------------------------------------------------------------------------
__global__ void __launch_bounds__(256) k1_proj(
    const float* __restrict__ x, const float* __restrict__ W1,
    const float* __restrict__ b1, const float* __restrict__ W2,
    const float* __restrict__ b2) {
    __shared__ __align__(16) float sx[2][4][68];   // x rows, pitch 68
    __shared__ float sUV[2][32];                   // warp partials [sel][w*4+nn]

    const int tid = threadIdx.x;
    const int n0 = blockIdx.x * 4;

    #pragma unroll
    for (int k = 0; k < 2; ++k) {             // x: 512 floats
        int l = k * 256 + tid;
        int b = l >> 8, node = (l >> 6) & 3, t = l & 63;
        sx[b][node][t] = x[((b << 10) + n0 + node) * 64 + t];
    }
    __syncthreads();

    const int h = tid >> 2;       // 0..63
    const int nn = tid & 3;       // 0..3
    const float4* __restrict__ wrow = (const float4*)(W1 + h * 128);

    float p0 = 0.f, p1 = 0.f, q0 = 0.f, q1 = 0.f;
    #pragma unroll
    for (int tt = 0; tt < 16; ++tt) {
        float4 wa = __ldg(&wrow[tt]);
        float4 wb = __ldg(&wrow[16 + tt]);
        float4 xa = *(const float4*)&sx[0][nn][tt * 4];
        float4 xb = *(const float4*)&sx[1][nn][tt * 4];
        p0 = fmaf(xa.x, wa.x, p0); p0 = fmaf(xa.y, wa.y, p0);
        p0 = fmaf(xa.z, wa.z, p0); p0 = fmaf(xa.w, wa.w, p0);
        p1 = fmaf(xb.x, wa.x, p1); p1 = fmaf(xb.y, wa.y, p1);
        p1 = fmaf(xb.z, wa.z, p1); p1 = fmaf(xb.w, wa.w, p1);
        q0 = fmaf(xa.x, wb.x, q0); q0 = fmaf(xa.y, wb.y, q0);
        q0 = fmaf(xa.z, wb.z, q0); q0 = fmaf(xa.w, wb.w, q0);
        q1 = fmaf(xb.x, wb.x, q1); q1 = fmaf(xb.y, wb.y, q1);
        q1 = fmaf(xb.z, wb.z, q1); q1 = fmaf(xb.w, wb.w, q1);
    }
    float bb = __ldg(&b1[h]);
    q0 += bb; q1 += bb;

    g_p[h * 1024 + n0 + nn]         = p0;
    g_p[65536 + h * 1024 + n0 + nn] = p1;
    g_q[h * 1024 + n0 + nn]         = q0;
    g_q[65536 + h * 1024 + n0 + nn] = q1;

    float w2h = __ldg(&W2[h]);
    float ru = w2h * (p0 + p1), rv = w2h * (q0 + q1);
    #pragma unroll
    for (int m = 16; m >= 4; m >>= 1) {
        ru += __shfl_down_sync(0xffffffffu, ru, m);
        rv += __shfl_down_sync(0xffffffffu, rv, m);
    }
    if ((tid & 31) < 4) {
        int w = tid >> 5;
        sUV[0][w * 4 + nn] = ru;
        sUV[1][w * 4 + nn] = rv;
    }
    __syncthreads();
    if (tid < 8) {
        int sel = tid >> 2, n2 = tid & 3;
        float acc = 0.f;
        #pragma unroll
        for (int w = 0; w < 8; ++w) acc += sUV[sel][w * 4 + n2];
        if (sel == 0) g_U[n0 + n2] = 0.2525f * acc;
        else          g_V[n0 + n2] = 0.2525f * acc + __ldg(&b2[0]);
    }
}

// ---------------------------------------------------------------------------
// Kernel 2: pairwise |z| accumulation + fused gumbel/argmax + finisher tail.
// Tile 64x64, grid (16,16); block 16x16 threads, 4i x 4j x 2b per thread.
// Batch-SPLIT smem (conflict-free q loads): ps[2][32][64] + qs[2][32][64]
// = 32KB, h chunked by 32.
// ---------------------------------------------------------------------------
__global__ void __launch_bounds__(256) k2_pair(const float* __restrict__ W2,
                                               const float* __restrict__ gu,
                                               float* __restrict__ out) {
    __shared__ __align__(16) float ps[2][32][64];  // [b][h][i]
    __shared__ __align__(16) float qs[2][32][64];  // [b][h][j]
    __shared__ float sw[64];
    __shared__ int s_old;

    const int tx = threadIdx.x, ty = threadIdx.y;
    const int tid = ty * 16 + tx;
    const int bx = blockIdx.x, by = blockIdx.y;
    const int i0 = by * 64, j0 = bx * 64;

    if (tid < 64) sw[tid] = 0.2475f * W2[tid];

    float acc[4][4];
    #pragma unroll
    for (int r = 0; r < 4; ++r)
        #pragma unroll
        for (int c = 0; c < 4; ++c) acc[r][c] = 0.f;

    #pragma unroll
    for (int hc = 0; hc < 2; ++hc) {
        const int hb = hc * 32;
        __syncthreads();   // protect prior chunk (and sw on first iter)
        // fill: ps/qs each 1024 float4; index l: b = l>>9, hh = (l>>4)&31, f4 = l&15
        #pragma unroll
        for (int k = 0; k < 4; ++k) {
            int l = k * 256 + tid;
            int b = l >> 9, hh = (l >> 4) & 31, f4 = l & 15;
            *(float4*)&ps[b][hh][f4 << 2] =
                *(const float4*)&g_p[b * 65536 + (hb + hh) * 1024 + i0 + (f4 << 2)];
            *(float4*)&qs[b][hh][f4 << 2] =
                *(const float4*)&g_q[b * 65536 + (hb + hh) * 1024 + j0 + (f4 << 2)];
        }
        __syncthreads();

        #pragma unroll 4
        for (int h = 0; h < 32; ++h) {
            float w = sw[hb + h];
            float4 p0v = *(const float4*)&ps[0][h][ty << 2];  // broadcast per ty
            float4 p1v = *(const float4*)&ps[1][h][ty << 2];
            float4 q0v = *(const float4*)&qs[0][h][tx << 2];  // lane-consecutive
            float4 q1v = *(const float4*)&qs[1][h][tx << 2];
            float p0a[4] = {p0v.x, p0v.y, p0v.z, p0v.w};
            float p1a[4] = {p1v.x, p1v.y, p1v.z, p1v.w};
            float q0a[4] = {q0v.x, q0v.y, q0v.z, q0v.w};
            float q1a[4] = {q1v.x, q1v.y, q1v.z, q1v.w};
            #pragma unroll
            for (int r = 0; r < 4; ++r)
                #pragma unroll
                for (int c = 0; c < 4; ++c) {
                    float z0 = p0a[r] + q0a[c];
                    float z1 = p1a[r] + q1a[c];
                    acc[r][c] = fmaf(w, fabsf(z0), acc[r][c]);
                    acc[r][c] = fmaf(w, fabsf(z1), acc[r][c]);
                }
        }
    }

    float u[4], v[4];
    #pragma unroll
    for (int r = 0; r < 4; ++r) u[r] = g_U[i0 + (ty << 2) + r];
    #pragma unroll
    for (int c = 0; c < 4; ++c) v[c] = g_V[j0 + (tx << 2) + c];

    // zero-fill this out tile (ones written by the finisher tail)
    const float4 z4 = make_float4(0.f, 0.f, 0.f, 0.f);
    #pragma unroll
    for (int r = 0; r < 4; ++r)
        *(float4*)&out[(i0 + (ty << 2) + r) * 1024 + j0 + (tx << 2)] = z4;

    // gumbel + per-row argmax across the 16 tx lanes
    #pragma unroll
    for (int r = 0; r < 4; ++r) {
        const int row = i0 + (ty << 2) + r;
        float4 uu = *(const float4*)&gu[row * 1024 + j0 + (tx << 2)];
        float gq[4];
        gq[0] = -__logf(-__logf(uu.x + 1e-10f) + 1e-10f);
        gq[1] = -__logf(-__logf(uu.y + 1e-10f) + 1e-10f);
        gq[2] = -__logf(-__logf(uu.z + 1e-10f) + 1e-10f);
        gq[3] = -__logf(-__logf(uu.w + 1e-10f) + 1e-10f);
        float bv = -3.0e38f; int bj = 1 << 30;
        #pragma unroll
        for (int c = 0; c < 4; ++c) {
            float val = acc[r][c] + u[r] + v[c] + gq[c];
            int j = j0 + (tx << 2) + c;
            if (val > bv || (val == bv && j < bj)) { bv = val; bj = j; }
        }
        #pragma unroll
        for (int m = 1; m < 16; m <<= 1) {
            float ov = __shfl_xor_sync(0xffffffffu, bv, m);
            int   oj = __shfl_xor_sync(0xffffffffu, bj, m);
            if (ov > bv || (ov == bv && oj < bj)) { bv = ov; bj = oj; }
        }
        if (tx == 0) {
            g_pv[row * 16 + bx] = bv;
            g_pi[row * 16 + bx] = bj;
        }
    }

    // ------- finisher tail: 16th block of row-band reduces + scatters -------
    __threadfence();
    __syncthreads();
    if (tid == 0) s_old = atomicAdd(&g_rowcnt[by], 1);
    __syncthreads();
    if (s_old == 15) {
        __threadfence();               // see all partials + zero-fills
        if (tid < 64) {
            const int row = by * 64 + tid;
            float bv = -3.0e38f; int bj = 1 << 30;
            #pragma unroll
            for (int k4 = 0; k4 < 4; ++k4) {
                float4 v4 = *(const float4*)&g_pv[row * 16 + k4 * 4];
                int4   j4 = *(const int4*)&g_pi[row * 16 + k4 * 4];
                float vv[4] = {v4.x, v4.y, v4.z, v4.w};
                int   jj[4] = {j4.x, j4.y, j4.z, j4.w};
                #pragma unroll
                for (int k = 0; k < 4; ++k)
                    if (vv[k] > bv || (vv[k] == bv && jj[k] < bj)) { bv = vv[k]; bj = jj[k]; }
            }
            out[row * 1024 + bj] = 1.0f;
        }
    }
    // last block overall resets tail state for the next graph replay
    if (tid == 0) {
        int old2 = atomicAdd(&g_done, 1);
        if (old2 == 255) {
            #pragma unroll
            for (int s = 0; s < 16; ++s) g_rowcnt[s] = 0;
            g_done = 0;
        }
    }
}

// ---------------------------------------------------------------------------
extern "C" void kernel_launch(void* const* d_in, const int* in_sizes, int n_in,
                              void* d_out, int out_size) {
    const float* x  = (const float*)d_in[0];   // [2,1024,64]
    const float* W1 = (const float*)d_in[1];   // [64,128]
    const float* b1 = (const float*)d_in[2];   // [64]
    const float* W2 = (const float*)d_in[3];   // [1,64]
    const float* b2 = (const float*)d_in[4];   // [1]
    const float* gu = (const float*)d_in[5];   // [1024,1024]
    float* out = (float*)d_out;                // [1024,1024] fp32

    k1_proj<<<256, 256>>>(x, W1, b1, W2, b2);
    k2_pair<<<dim3(16, 16), dim3(16, 16)>>>(W2, gu, out);
}